// round 14
// baseline (speedup 1.0000x reference)
#include <cuda_runtime.h>
#include <cuda_fp16.h>
#include <cstdint>

// ---------------- problem constants ----------------
constexpr int SEQ   = 2048;
constexpr int DMOD  = 512;
constexpr int NB    = 2;
constexpr int DEP   = 64;
constexpr int HB    = 16;

// fp16 scratch (q pre-scaled by log2e/8): q,k [hb][s][d]; vT [hb][d][s]
__device__ __half g_q_hi[HB * SEQ * DEP];
__device__ __half g_k_hi[HB * SEQ * DEP];
__device__ __half g_vT_hi[HB * DEP * SEQ];
__device__ uint32_t g_mbits[NB * SEQ * (SEQ / 32)];   // 1 bit per mask entry
// fp16 inputs for QKV mma (1-chain)
__device__ __half g_x_hi[NB * SEQ * DMOD];
__device__ __half g_wT_hi[3 * DMOD * DMOD];   // [z][n][k]

// ---------------- helpers ----------------
__device__ __forceinline__ uint32_t smem_u32(const void* p) {
    uint32_t a;
    asm("{ .reg .u64 t; cvta.to.shared.u64 t, %1; cvt.u32.u64 %0, t; }" : "=r"(a) : "l"(p));
    return a;
}
__device__ __forceinline__ uint32_t pack_h(float a, float b) {
    __half2 h = __floats2half2_rn(a, b);
    return *(uint32_t*)&h;
}
__device__ __forceinline__ float ex2(float x) {
    float r;
    asm("ex2.approx.ftz.f32 %0, %1;" : "=f"(r) : "f"(x));
    return r;
}
__device__ __forceinline__ void mma_f16(float* d, const uint32_t* a, uint32_t b0, uint32_t b1) {
    asm volatile("mma.sync.aligned.m16n8k16.row.col.f32.f16.f16.f32 "
        "{%0,%1,%2,%3}, {%4,%5,%6,%7}, {%8,%9}, {%0,%1,%2,%3};"
        : "+f"(d[0]), "+f"(d[1]), "+f"(d[2]), "+f"(d[3])
        : "r"(a[0]), "r"(a[1]), "r"(a[2]), "r"(a[3]), "r"(b0), "r"(b1));
}
__device__ __forceinline__ void ldsm4(uint32_t& r0, uint32_t& r1, uint32_t& r2, uint32_t& r3,
                                      uint32_t addr) {
    asm volatile("ldmatrix.sync.aligned.m8n8.x4.shared.b16 {%0,%1,%2,%3}, [%4];"
        : "=r"(r0), "=r"(r1), "=r"(r2), "=r"(r3) : "r"(addr));
}
__device__ __forceinline__ void cp16(uint32_t saddr, const void* g) {
    asm volatile("cp.async.cg.shared.global [%0], [%1], 16;" :: "r"(saddr), "l"(g));
}
#define CP_COMMIT() asm volatile("cp.async.commit_group;" ::: "memory")
#define CP_WAIT0()  asm volatile("cp.async.wait_group 0;" ::: "memory")

// ---------------- fused prep: mask -> bits, X -> fp16, W transpose -> fp16 ----------------
constexpr int MASK_BLOCKS  = (NB * SEQ * SEQ) / (256 * 32);     // 1024 (1 word/thread)
constexpr int PREPX_BLOCKS = (NB * SEQ * DMOD) / (256 * 4);     // 2048
constexpr int PREPW_BLOCKS = 3 * 16 * 16;                       // 768

__global__ __launch_bounds__(256)
void prep_all(const float* __restrict__ mask, const float* __restrict__ X,
              const float* __restrict__ Wq, const float* __restrict__ Wk,
              const float* __restrict__ Wv) {
    if (blockIdx.x < MASK_BLOCKS) {
        // one 32-bit mask word per thread: 8 independent LDG.128, no votes
        size_t w = (size_t)blockIdx.x * 256 + threadIdx.x;
        const float4* mp = (const float4*)(mask + w * 32);
        uint32_t bits = 0;
        #pragma unroll
        for (int i = 0; i < 8; i++) {
            float4 v = mp[i];
            bits |= (v.x != 0.f ? 1u : 0u) << (4 * i);
            bits |= (v.y != 0.f ? 2u : 0u) << (4 * i);
            bits |= (v.z != 0.f ? 4u : 0u) << (4 * i);
            bits |= (v.w != 0.f ? 8u : 0u) << (4 * i);
        }
        g_mbits[w] = bits;
    } else if (blockIdx.x < MASK_BLOCKS + PREPX_BLOCKS) {
        size_t i = ((size_t)(blockIdx.x - MASK_BLOCKS) * 256 + threadIdx.x) * 4;
        float4 v = *(const float4*)(X + i);
        *(uint2*)(g_x_hi + i) = make_uint2(pack_h(v.x, v.y), pack_h(v.z, v.w));
    } else {
        const int wb = blockIdx.x - MASK_BLOCKS - PREPX_BLOCKS;   // 0..767
        const int z = wb >> 8;
        const int rem = wb & 255;
        const float* W = (z == 0) ? Wq : (z == 1) ? Wk : Wv;
        __shared__ float t[32][33];
        const int tx = threadIdx.x & 31, ty = threadIdx.x >> 5;   // (32, 8)
        const int n0 = (rem & 15) * 32, k0 = (rem >> 4) * 32;
        #pragma unroll
        for (int yy = 0; yy < 4; yy++)
            t[ty + 8 * yy][tx] = W[(size_t)(k0 + ty + 8 * yy) * DMOD + n0 + tx];
        __syncthreads();
        const size_t zoff = (size_t)z * DMOD * DMOD;
        #pragma unroll
        for (int yy = 0; yy < 4; yy++) {
            int a = ty + 8 * yy;
            g_wT_hi[zoff + (size_t)(n0 + a) * DMOD + k0 + tx] = __float2half_rn(t[tx][a]);
        }
    }
}

// ---------------- QKV projection: 1-chain fp16 mma.sync, 64x64 tiles, occ 4 ----------------
constexpr int CPAD = 40;
constexpr int CROWB = CPAD * 2;
constexpr int XBYTES = 64 * CPAD * 2;              // 5120
constexpr int QSTG = XBYTES + 64 * CPAD * 2;       // 10240 bytes per stage

__global__ __launch_bounds__(128, 4)
void qkv_mma(const float* __restrict__ bq, const float* __restrict__ bk,
             const float* __restrict__ bv) {
    extern __shared__ __align__(16) uint8_t dynsmem[];   // 2 * QSTG

    const int tid = threadIdx.x;
    const int lane = tid & 31, wn = tid >> 5;        // 4 warps, each owns 16 N-cols
    const int bm = blockIdx.y * 64, bn = blockIdx.x * 64;
    const int z = blockIdx.z;
    const float* bias = (z == 0) ? bq : (z == 1) ? bk : bv;
    const size_t zoff = (size_t)z * DMOD * DMOD;

    const int g = lane >> 2, c0 = (lane & 3) * 2;

    float acc[4][2][4];
    #pragma unroll
    for (int mt = 0; mt < 4; mt++)
        #pragma unroll
        for (int nt = 0; nt < 2; nt++)
            #pragma unroll
            for (int i = 0; i < 4; i++) acc[mt][nt][i] = 0.f;

    const uint32_t sbase = smem_u32(dynsmem);
    const uint32_t aA0 = sbase + (uint32_t)(lane & 15) * CROWB + ((lane & 16) ? 16 : 0);
    const int lrowB = (lane & 7) + ((lane & 16) ? 8 : 0);
    const uint32_t aB0 = sbase + XBYTES + (uint32_t)(wn * 16 + lrowB) * CROWB + ((lane & 8) ? 16 : 0);

    auto issue = [&](int ch, uint32_t sb) {
        const int k0 = ch * 32;
        #pragma unroll
        for (int p = 0; p < 2; p++) {
            int idx = tid + p * 128;
            int r = idx >> 2, c8 = (idx & 3) * 8;
            cp16(sb + (uint32_t)(r * CPAD + c8) * 2,
                 g_x_hi + (size_t)(bm + r) * DMOD + k0 + c8);
            cp16(sb + XBYTES + (uint32_t)(r * CPAD + c8) * 2,
                 g_wT_hi + zoff + (size_t)(bn + r) * DMOD + k0 + c8);
        }
        CP_COMMIT();
    };

    issue(0, sbase);

    for (int ch = 0; ch < 16; ch++) {
        CP_WAIT0();
        __syncthreads();
        if (ch < 15) issue(ch + 1, sbase + ((ch + 1) & 1) * QSTG);

        const uint32_t bo = (uint32_t)(ch & 1) * QSTG;
        const uint32_t aA = aA0 + bo, aB = aB0 + bo;

        #pragma unroll
        for (int ks = 0; ks < 2; ks++) {
            uint32_t ah[4][4];
            #pragma unroll
            for (int mt = 0; mt < 4; mt++)
                ldsm4(ah[mt][0], ah[mt][1], ah[mt][2], ah[mt][3], aA + mt * 16 * CROWB + ks * 32);
            uint32_t b0, b1, b2, b3;
            ldsm4(b0, b1, b2, b3, aB + ks * 32);
            #pragma unroll
            for (int mt = 0; mt < 4; mt++) {
                mma_f16(acc[mt][0], ah[mt], b0, b1);
                mma_f16(acc[mt][1], ah[mt], b2, b3);
            }
        }
        __syncthreads();
    }

    if (z < 2) {
        // Q/K: q scaled by log2e/8 (softmax uses exp2)
        __half* oh = (z == 0) ? g_q_hi : g_k_hi;
        const float scale = (z == 0) ? 0.125f * 1.44269504088896f : 1.0f;
        #pragma unroll
        for (int nt = 0; nt < 2; nt++) {
            int coln = bn + wn * 16 + nt * 8 + c0;
            int h = coln >> 6, dd = coln & 63;
            float b0v = bias[coln], b1v = bias[coln + 1];
            #pragma unroll
            for (int mt = 0; mt < 4; mt++) {
                int m1 = bm + mt * 16 + g;
                int bb = m1 >> 11, ss = m1 & 2047;
                size_t base = ((size_t)((h * NB + bb) * SEQ + ss)) * DEP + dd;
                *(uint32_t*)(oh + base) =
                    pack_h((acc[mt][nt][0] + b0v) * scale, (acc[mt][nt][1] + b1v) * scale);
                *(uint32_t*)(oh + base + 8 * DEP) =
                    pack_h((acc[mt][nt][2] + b0v) * scale, (acc[mt][nt][3] + b1v) * scale);
            }
        }
    } else {
        // V: transpose through smem to [hb][d][s]; all 4 warps, 64x17 floats each
        float* stg = (float*)dynsmem + wn * (64 * 17);
        __syncthreads();
        #pragma unroll
        for (int mt = 0; mt < 4; mt++)
            #pragma unroll
            for (int nt = 0; nt < 2; nt++) {
                int rb = (mt * 16 + g) * 17 + nt * 8 + c0;
                stg[rb]              = acc[mt][nt][0];
                stg[rb + 1]          = acc[mt][nt][1];
                stg[rb + 8 * 17]     = acc[mt][nt][2];
                stg[rb + 8 * 17 + 1] = acc[mt][nt][3];
            }
        __syncwarp();
        const int cc = lane & 15, shalf = lane >> 4;
        const int coln = bn + wn * 16 + cc;
        const int h = coln >> 6, dd = coln & 63;
        const float bvv = bias[coln];
        const int bb = bm >> 11, ss0 = bm & 2047;
        const size_t base = ((size_t)((h * NB + bb) * DEP + dd)) * SEQ + ss0;
        #pragma unroll
        for (int s8 = 0; s8 < 4; s8++) {
            const int sblk = shalf * 4 + s8;
            uint32_t hv[4];
            #pragma unroll
            for (int j = 0; j < 4; j++) {
                float v0 = stg[(sblk * 8 + 2 * j) * 17 + cc] + bvv;
                float v1 = stg[(sblk * 8 + 2 * j + 1) * 17 + cc] + bvv;
                hv[j] = pack_h(v0, v1);
            }
            *(uint4*)(g_vT_hi + base + sblk * 8) = make_uint4(hv[0], hv[1], hv[2], hv[3]);
        }
    }
}

// ---------------- mma.sync flash attention: 128 q-rows/CTA, 8 warps, ex2+sel ----------------
constexpr int KPAD = 72;
constexpr int ROWB = KPAD * 2;
constexpr int ABUF = 64 * KPAD;          // halves per array per stage

__global__ __launch_bounds__(256, 2)
void attn_mma(float* __restrict__ out) {
    __shared__ __half sK[2][ABUF];
    __shared__ __half sV[2][ABUF];

    const int tid  = threadIdx.x;
    const int lane = tid & 31;
    const int wid  = tid >> 5;           // 0..7
    const int q0   = blockIdx.x * 128;
    const int hb   = blockIdx.y;
    const int b    = hb & 1, h = hb >> 1;
    const int row0 = q0 + wid * 16;
    const int g    = lane >> 2;
    const int c0   = (lane & 3) * 2;

    // ---- Q fragments in registers ----
    uint32_t qhi[4][4];
    {
        const size_t r1 = ((size_t)hb * SEQ + row0 + g) * DEP;
        const size_t r2 = ((size_t)hb * SEQ + row0 + g + 8) * DEP;
        #pragma unroll
        for (int ks = 0; ks < 4; ks++) {
            int c = ks * 16 + c0;
            qhi[ks][0] = *(const uint32_t*)(g_q_hi + r1 + c);
            qhi[ks][1] = *(const uint32_t*)(g_q_hi + r2 + c);
            qhi[ks][2] = *(const uint32_t*)(g_q_hi + r1 + c + 8);
            qhi[ks][3] = *(const uint32_t*)(g_q_hi + r2 + c + 8);
        }
    }

    float O[8][4];
    #pragma unroll
    for (int nt = 0; nt < 8; nt++)
        #pragma unroll
        for (int i = 0; i < 4; i++) O[nt][i] = 0.f;
    float lg = 0.f, lg8 = 0.f;

    const int lrow = (lane & 7) + ((lane & 16) ? 8 : 0);
    const int lcol = (lane & 8) ? 16 : 0;
    const uint32_t aK0 = smem_u32(sK[0]) + lrow * ROWB + lcol;
    const uint32_t aV0 = smem_u32(sV[0]) + lrow * ROWB + lcol;
    const uint32_t sKb = smem_u32(sK[0]);
    const uint32_t sVb = smem_u32(sV[0]);
    constexpr uint32_t STGB = ABUF * 2;  // bytes per stage per array

    // packed mask bit rows (64 words per row)
    const uint32_t* mb1 = g_mbits + ((size_t)b * SEQ + row0 + g) * (SEQ / 32);
    const uint32_t* mb2 = mb1 + 8 * (SEQ / 32);

    const __half* kh = g_k_hi  + (size_t)hb * SEQ * DEP;
    const __half* vh = g_vT_hi + (size_t)hb * DEP * SEQ;

    auto issue_tile = [&](int it, int buf) {
        const int k0 = it * 64;
        const uint32_t kb = sKb + buf * STGB;
        const uint32_t vb = sVb + buf * STGB;
        #pragma unroll
        for (int p = 0; p < 2; p++) {
            int idx = tid + p * 256;
            int r = idx >> 3, c = idx & 7;
            uint32_t so = (uint32_t)(r * KPAD + c * 8) * 2;
            cp16(kb + so, kh + ((size_t)(k0 + r)) * DEP + c * 8);
            cp16(vb + so, vh + ((size_t)r) * SEQ + k0 + c * 8);
        }
        CP_COMMIT();
    };

    issue_tile(0, 0);

    for (int it = 0; it < 32; it++) {
        CP_WAIT0();
        __syncthreads();
        if (it < 31) issue_tile(it + 1, (it + 1) & 1);

        const uint32_t aK = aK0 + (it & 1) * STGB;
        const uint32_t aV = aV0 + (it & 1) * STGB;

        // mask bit-words for this 64-col tile (2 rows x 64 bits)
        const uint2 w1 = *(const uint2*)(mb1 + 2 * it);
        const uint2 w2 = *(const uint2*)(mb2 + 2 * it);

        // ---- S = Q K^T ----
        float S[8][4];
        #pragma unroll
        for (int nt = 0; nt < 8; nt++)
            #pragma unroll
            for (int i = 0; i < 4; i++) S[nt][i] = 0.f;

        #pragma unroll
        for (int ks = 0; ks < 4; ks++) {
            #pragma unroll
            for (int ntp = 0; ntp < 4; ntp++) {
                uint32_t b0, b1, b2, b3;
                ldsm4(b0, b1, b2, b3, aK + ntp * (16 * ROWB) + ks * 32);
                mma_f16(S[2 * ntp],     qhi[ks], b0, b1);
                mma_f16(S[2 * ntp + 1], qhi[ks], b2, b3);
            }
        }

        // ---- softmax: p = masked ? 0 : 2^S  (log2e folded into Q; single MUFU EX2) ----
        uint32_t phi01[8], phi23[8];
        #pragma unroll
        for (int nt = 0; nt < 8; nt++) {
            const uint32_t wa = (nt < 4) ? w1.x : w1.y;
            const uint32_t wb = (nt < 4) ? w2.x : w2.y;
            const int sh = (nt * 8 + c0) & 31;
            float p0 = ex2(S[nt][0]);
            float p1 = ex2(S[nt][1]);
            float p2 = ex2(S[nt][2]);
            float p3 = ex2(S[nt][3]);
            p0 = ((wa >> sh) & 1u) ? 0.f : p0;
            p1 = ((wa >> (sh + 1)) & 1u) ? 0.f : p1;
            p2 = ((wb >> sh) & 1u) ? 0.f : p2;
            p3 = ((wb >> (sh + 1)) & 1u) ? 0.f : p3;
            lg  += p0 + p1;
            lg8 += p2 + p3;
            phi01[nt] = pack_h(p0, p1);
            phi23[nt] = pack_h(p2, p3);
        }

        // ---- O += P V ----
        #pragma unroll
        for (int ks = 0; ks < 4; ks++) {
            uint32_t pa[4] = {phi01[2 * ks], phi23[2 * ks], phi01[2 * ks + 1], phi23[2 * ks + 1]};
            #pragma unroll
            for (int ntp = 0; ntp < 4; ntp++) {
                uint32_t b0, b1, b2, b3;
                ldsm4(b0, b1, b2, b3, aV + ntp * (16 * ROWB) + ks * 32);
                mma_f16(O[2 * ntp],     pa, b0, b1);
                mma_f16(O[2 * ntp + 1], pa, b2, b3);
            }
        }
    }

    // reduce row sums across the 4 lanes sharing each row
    lg  += __shfl_xor_sync(0xffffffffu, lg, 1);
    lg  += __shfl_xor_sync(0xffffffffu, lg, 2);
    lg8 += __shfl_xor_sync(0xffffffffu, lg8, 1);
    lg8 += __shfl_xor_sync(0xffffffffu, lg8, 2);
    const float inv1 = 1.f / lg, inv2 = 1.f / lg8;

    float* o1 = out + ((size_t)b * SEQ + row0 + g) * DMOD + h * DEP + c0;
    float* o2 = out + ((size_t)b * SEQ + row0 + g + 8) * DMOD + h * DEP + c0;
    #pragma unroll
    for (int nt = 0; nt < 8; nt++) {
        float2 w1v = make_float2(O[nt][0] * inv1, O[nt][1] * inv1);
        float2 w2v = make_float2(O[nt][2] * inv2, O[nt][3] * inv2);
        *(float2*)(o1 + nt * 8) = w1v;
        *(float2*)(o2 + nt * 8) = w2v;
    }
}

// ---------------- launch ----------------
extern "C" void kernel_launch(void* const* d_in, const int* in_sizes, int n_in,
                              void* d_out, int out_size) {
    const float* x    = (const float*)d_in[0];
    const float* mask = (const float*)d_in[1];
    const float* Wq   = (const float*)d_in[2];
    const float* bq   = (const float*)d_in[3];
    const float* Wk   = (const float*)d_in[4];
    const float* bk   = (const float*)d_in[5];
    const float* Wv   = (const float*)d_in[6];
    const float* bv   = (const float*)d_in[7];
    float* out = (float*)d_out;

    cudaFuncSetAttribute(qkv_mma, cudaFuncAttributeMaxDynamicSharedMemorySize, 2 * QSTG);

    prep_all<<<MASK_BLOCKS + PREPX_BLOCKS + PREPW_BLOCKS, 256>>>(mask, x, Wq, Wk, Wv);

    dim3 gqkv(DMOD / 64, (NB * SEQ) / 64, 3);            // (8, 64, 3) = 1536 CTAs
    qkv_mma<<<gqkv, 128, 2 * QSTG>>>(bq, bk, bv);

    dim3 gattn(SEQ / 128, HB);                           // (16, 16) = 256 CTAs
    attn_mma<<<gattn, 256>>>(out);
}

// round 16
// speedup vs baseline: 1.0787x; 1.0787x over previous
#include <cuda_runtime.h>
#include <cuda_fp16.h>
#include <cstdint>

// ---------------- problem constants ----------------
constexpr int SEQ   = 2048;
constexpr int DMOD  = 512;
constexpr int NB    = 2;
constexpr int DEP   = 64;
constexpr int HB    = 16;

// fp16 scratch (q pre-scaled by log2e/8): q,k [hb][s][d]; vT [hb][d][s]
__device__ __half g_q_hi[HB * SEQ * DEP];
__device__ __half g_k_hi[HB * SEQ * DEP];
__device__ __half g_vT_hi[HB * DEP * SEQ];
// mask bits, PERMUTED within each 32-bit word: bit (8a + r) = column (4r + a)
__device__ uint32_t g_mbits[NB * SEQ * (SEQ / 32)];
// fp16 inputs for QKV mma (1-chain)
__device__ __half g_x_hi[NB * SEQ * DMOD];
__device__ __half g_wT_hi[3 * DMOD * DMOD];   // [z][n][k]

// ---------------- helpers ----------------
__device__ __forceinline__ uint32_t smem_u32(const void* p) {
    uint32_t a;
    asm("{ .reg .u64 t; cvta.to.shared.u64 t, %1; cvt.u32.u64 %0, t; }" : "=r"(a) : "l"(p));
    return a;
}
__device__ __forceinline__ uint32_t pack_h(float a, float b) {
    __half2 h = __floats2half2_rn(a, b);
    return *(uint32_t*)&h;
}
__device__ __forceinline__ float ex2(float x) {
    float r;
    asm("ex2.approx.ftz.f32 %0, %1;" : "=f"(r) : "f"(x));
    return r;
}
__device__ __forceinline__ void mma_f16(float* d, const uint32_t* a, uint32_t b0, uint32_t b1) {
    asm volatile("mma.sync.aligned.m16n8k16.row.col.f32.f16.f16.f32 "
        "{%0,%1,%2,%3}, {%4,%5,%6,%7}, {%8,%9}, {%0,%1,%2,%3};"
        : "+f"(d[0]), "+f"(d[1]), "+f"(d[2]), "+f"(d[3])
        : "r"(a[0]), "r"(a[1]), "r"(a[2]), "r"(a[3]), "r"(b0), "r"(b1));
}
__device__ __forceinline__ void ldsm4(uint32_t& r0, uint32_t& r1, uint32_t& r2, uint32_t& r3,
                                      uint32_t addr) {
    asm volatile("ldmatrix.sync.aligned.m8n8.x4.shared.b16 {%0,%1,%2,%3}, [%4];"
        : "=r"(r0), "=r"(r1), "=r"(r2), "=r"(r3) : "r"(addr));
}
__device__ __forceinline__ void cp16(uint32_t saddr, const void* g) {
    asm volatile("cp.async.cg.shared.global [%0], [%1], 16;" :: "r"(saddr), "l"(g));
}
#define CP_COMMIT() asm volatile("cp.async.commit_group;" ::: "memory")
#define CP_WAIT0()  asm volatile("cp.async.wait_group 0;" ::: "memory")

// ---------------- fused prep: mask -> permuted bits, X -> fp16, W transpose -> fp16 ----------------
constexpr int MASK_BLOCKS  = (NB * SEQ * SEQ) / (8 * 2048);     // 1024 (8 warps x 2048 elems)
constexpr int PREPX_BLOCKS = (NB * SEQ * DMOD) / (256 * 4);     // 2048
constexpr int PREPW_BLOCKS = 3 * 16 * 16;                       // 768

__global__ __launch_bounds__(256)
void prep_all(const float* __restrict__ mask, const float* __restrict__ X,
              const float* __restrict__ Wq, const float* __restrict__ Wk,
              const float* __restrict__ Wv) {
    if (blockIdx.x < MASK_BLOCKS) {
        // float4 coalesced loads + 4 ballots per 128 elems; words stored with
        // permuted bit order: bit (8a + r) = column (4r + a) within the 32-group.
        const int warp = blockIdx.x * 8 + (threadIdx.x >> 5);
        const int lane = threadIdx.x & 31;
        const float4* mp = (const float4*)mask + (size_t)warp * 512 + lane;
        uint32_t* ob = g_mbits + (size_t)warp * 64;
        #pragma unroll
        for (int i = 0; i < 16; i++) {
            float4 v = mp[i * 32];
            uint32_t b0 = __ballot_sync(0xffffffffu, v.x != 0.f);
            uint32_t b1 = __ballot_sync(0xffffffffu, v.y != 0.f);
            uint32_t b2 = __ballot_sync(0xffffffffu, v.z != 0.f);
            uint32_t b3 = __ballot_sync(0xffffffffu, v.w != 0.f);
            if (lane < 4) {
                uint32_t t01 = __byte_perm(b0, b1, 0x0000 | lane | ((4 + lane) << 4));
                uint32_t t23 = __byte_perm(b2, b3, 0x0000 | lane | ((4 + lane) << 4));
                ob[i * 4 + lane] = __byte_perm(t01, t23, 0x5410);
            }
        }
    } else if (blockIdx.x < MASK_BLOCKS + PREPX_BLOCKS) {
        size_t i = ((size_t)(blockIdx.x - MASK_BLOCKS) * 256 + threadIdx.x) * 4;
        float4 v = *(const float4*)(X + i);
        *(uint2*)(g_x_hi + i) = make_uint2(pack_h(v.x, v.y), pack_h(v.z, v.w));
    } else {
        const int wb = blockIdx.x - MASK_BLOCKS - PREPX_BLOCKS;   // 0..767
        const int z = wb >> 8;
        const int rem = wb & 255;
        const float* W = (z == 0) ? Wq : (z == 1) ? Wk : Wv;
        __shared__ float t[32][33];
        const int tx = threadIdx.x & 31, ty = threadIdx.x >> 5;   // (32, 8)
        const int n0 = (rem & 15) * 32, k0 = (rem >> 4) * 32;
        #pragma unroll
        for (int yy = 0; yy < 4; yy++)
            t[ty + 8 * yy][tx] = W[(size_t)(k0 + ty + 8 * yy) * DMOD + n0 + tx];
        __syncthreads();
        const size_t zoff = (size_t)z * DMOD * DMOD;
        #pragma unroll
        for (int yy = 0; yy < 4; yy++) {
            int a = ty + 8 * yy;
            g_wT_hi[zoff + (size_t)(n0 + a) * DMOD + k0 + tx] = __float2half_rn(t[tx][a]);
        }
    }
}

// ---------------- QKV projection: 1-chain fp16 mma.sync, 64x128 tiles, occ 4 ----------------
constexpr int CPAD = 40;
constexpr int CROWB = CPAD * 2;
constexpr int XBYTES = 64 * CPAD * 2;              // 5120
constexpr int QSTG = XBYTES + 128 * CPAD * 2;      // 15360 bytes per stage

__global__ __launch_bounds__(128, 4)
void qkv_mma(const float* __restrict__ bq, const float* __restrict__ bk,
             const float* __restrict__ bv) {
    extern __shared__ __align__(16) uint8_t dynsmem[];   // 2 * QSTG

    const int tid = threadIdx.x;
    const int lane = tid & 31, wn = tid >> 5;        // 4 warps, each owns 32 N-cols
    const int bm = blockIdx.y * 64, bn = blockIdx.x * 128;
    const int z = blockIdx.z;
    const float* bias = (z == 0) ? bq : (z == 1) ? bk : bv;
    const size_t zoff = (size_t)z * DMOD * DMOD;

    const int g = lane >> 2, c0 = (lane & 3) * 2;

    float acc[4][4][4];
    #pragma unroll
    for (int mt = 0; mt < 4; mt++)
        #pragma unroll
        for (int nt = 0; nt < 4; nt++)
            #pragma unroll
            for (int i = 0; i < 4; i++) acc[mt][nt][i] = 0.f;

    const uint32_t sbase = smem_u32(dynsmem);
    const uint32_t aA0 = sbase + (uint32_t)(lane & 15) * CROWB + ((lane & 16) ? 16 : 0);
    const int lrowB = (lane & 7) + ((lane & 16) ? 8 : 0);
    const uint32_t aB0 = sbase + XBYTES + (uint32_t)(wn * 32 + lrowB) * CROWB + ((lane & 8) ? 16 : 0);

    auto issue = [&](int ch, uint32_t sb) {
        const int k0 = ch * 32;
        #pragma unroll
        for (int p = 0; p < 2; p++) {
            int idx = tid + p * 128;
            int r = idx >> 2, c8 = (idx & 3) * 8;
            cp16(sb + (uint32_t)(r * CPAD + c8) * 2,
                 g_x_hi + (size_t)(bm + r) * DMOD + k0 + c8);
        }
        #pragma unroll
        for (int p = 0; p < 4; p++) {
            int idx = tid + p * 128;
            int r = idx >> 2, c8 = (idx & 3) * 8;
            cp16(sb + XBYTES + (uint32_t)(r * CPAD + c8) * 2,
                 g_wT_hi + zoff + (size_t)(bn + r) * DMOD + k0 + c8);
        }
        CP_COMMIT();
    };

    issue(0, sbase);

    for (int ch = 0; ch < 16; ch++) {
        CP_WAIT0();
        __syncthreads();
        if (ch < 15) issue(ch + 1, sbase + ((ch + 1) & 1) * QSTG);

        const uint32_t bo = (uint32_t)(ch & 1) * QSTG;
        const uint32_t aA = aA0 + bo, aB = aB0 + bo;

        #pragma unroll
        for (int ks = 0; ks < 2; ks++) {
            uint32_t ah[4][4];
            #pragma unroll
            for (int mt = 0; mt < 4; mt++)
                ldsm4(ah[mt][0], ah[mt][1], ah[mt][2], ah[mt][3], aA + mt * 16 * CROWB + ks * 32);
            #pragma unroll
            for (int ntp = 0; ntp < 2; ntp++) {
                uint32_t b0, b1, b2, b3;
                ldsm4(b0, b1, b2, b3, aB + ntp * 16 * CROWB + ks * 32);
                #pragma unroll
                for (int mt = 0; mt < 4; mt++) {
                    mma_f16(acc[mt][2 * ntp],     ah[mt], b0, b1);
                    mma_f16(acc[mt][2 * ntp + 1], ah[mt], b2, b3);
                }
            }
        }
        __syncthreads();
    }

    if (z < 2) {
        // Q/K: q scaled by log2e/8 (softmax uses exp2)
        __half* oh = (z == 0) ? g_q_hi : g_k_hi;
        const float scale = (z == 0) ? 0.125f * 1.44269504088896f : 1.0f;
        #pragma unroll
        for (int nt = 0; nt < 4; nt++) {
            int coln = bn + wn * 32 + nt * 8 + c0;
            int h = coln >> 6, dd = coln & 63;
            float b0v = bias[coln], b1v = bias[coln + 1];
            #pragma unroll
            for (int mt = 0; mt < 4; mt++) {
                int m1 = bm + mt * 16 + g;
                int bb = m1 >> 11, ss = m1 & 2047;
                size_t base = ((size_t)((h * NB + bb) * SEQ + ss)) * DEP + dd;
                *(uint32_t*)(oh + base) =
                    pack_h((acc[mt][nt][0] + b0v) * scale, (acc[mt][nt][1] + b1v) * scale);
                *(uint32_t*)(oh + base + 8 * DEP) =
                    pack_h((acc[mt][nt][2] + b0v) * scale, (acc[mt][nt][3] + b1v) * scale);
            }
        }
    } else {
        // V: transpose through smem to [hb][d][s]; 2 phases x 2 warps
        float* stg = (float*)dynsmem + (tid >> 5 & 1) * (64 * 33);
        __syncthreads();
        #pragma unroll
        for (int phase = 0; phase < 2; phase++) {
            if ((wn >> 1) == phase) {
                #pragma unroll
                for (int mt = 0; mt < 4; mt++)
                    #pragma unroll
                    for (int nt = 0; nt < 4; nt++) {
                        int rb = (mt * 16 + g) * 33 + nt * 8 + c0;
                        stg[rb]              = acc[mt][nt][0];
                        stg[rb + 1]          = acc[mt][nt][1];
                        stg[rb + 8 * 33]     = acc[mt][nt][2];
                        stg[rb + 8 * 33 + 1] = acc[mt][nt][3];
                    }
                __syncwarp();
                int coln = bn + wn * 32 + lane;
                int h = coln >> 6, dd = coln & 63;
                float bvv = bias[coln];
                int bb = bm >> 11, ss0 = bm & 2047;
                size_t base = ((size_t)((h * NB + bb) * DEP + dd)) * SEQ + ss0;
                #pragma unroll
                for (int s8 = 0; s8 < 8; s8++) {
                    uint32_t hv[4];
                    #pragma unroll
                    for (int j = 0; j < 4; j++) {
                        float v0 = stg[(s8 * 8 + 2 * j) * 33 + lane] + bvv;
                        float v1 = stg[(s8 * 8 + 2 * j + 1) * 33 + lane] + bvv;
                        hv[j] = pack_h(v0, v1);
                    }
                    *(uint4*)(g_vT_hi + base + s8 * 8) = make_uint4(hv[0], hv[1], hv[2], hv[3]);
                }
            }
            __syncthreads();
        }
    }
}

// ---------------- mma.sync flash attention: 128 q-rows/CTA, 8 warps, ex2+sel ----------------
constexpr int KPAD = 72;
constexpr int ROWB = KPAD * 2;
constexpr int ABUF = 64 * KPAD;          // halves per array per stage

__global__ __launch_bounds__(256, 2)
void attn_mma(float* __restrict__ out) {
    __shared__ __half sK[2][ABUF];
    __shared__ __half sV[2][ABUF];

    const int tid  = threadIdx.x;
    const int lane = tid & 31;
    const int wid  = tid >> 5;           // 0..7
    const int q0   = blockIdx.x * 128;
    const int hb   = blockIdx.y;
    const int b    = hb & 1, h = hb >> 1;
    const int row0 = q0 + wid * 16;
    const int g    = lane >> 2;
    const int c0   = (lane & 3) * 2;

    // ---- Q fragments in registers ----
    uint32_t qhi[4][4];
    {
        const size_t r1 = ((size_t)hb * SEQ + row0 + g) * DEP;
        const size_t r2 = ((size_t)hb * SEQ + row0 + g + 8) * DEP;
        #pragma unroll
        for (int ks = 0; ks < 4; ks++) {
            int c = ks * 16 + c0;
            qhi[ks][0] = *(const uint32_t*)(g_q_hi + r1 + c);
            qhi[ks][1] = *(const uint32_t*)(g_q_hi + r2 + c);
            qhi[ks][2] = *(const uint32_t*)(g_q_hi + r1 + c + 8);
            qhi[ks][3] = *(const uint32_t*)(g_q_hi + r2 + c + 8);
        }
    }

    float O[8][4];
    #pragma unroll
    for (int nt = 0; nt < 8; nt++)
        #pragma unroll
        for (int i = 0; i < 4; i++) O[nt][i] = 0.f;
    float lg = 0.f, lg8 = 0.f;

    const int lrow = (lane & 7) + ((lane & 16) ? 8 : 0);
    const int lcol = (lane & 8) ? 16 : 0;
    const uint32_t aK0 = smem_u32(sK[0]) + lrow * ROWB + lcol;
    const uint32_t aV0 = smem_u32(sV[0]) + lrow * ROWB + lcol;
    const uint32_t sKb = smem_u32(sK[0]);
    const uint32_t sVb = smem_u32(sV[0]);
    constexpr uint32_t STGB = ABUF * 2;  // bytes per stage per array

    // packed mask bit rows (64 words per row, permuted bit order within words)
    const uint32_t* mb1 = g_mbits + ((size_t)b * SEQ + row0 + g) * (SEQ / 32);
    const uint32_t* mb2 = mb1 + 8 * (SEQ / 32);

    const __half* kh = g_k_hi  + (size_t)hb * SEQ * DEP;
    const __half* vh = g_vT_hi + (size_t)hb * DEP * SEQ;

    auto issue_tile = [&](int it, int buf) {
        const int k0 = it * 64;
        const uint32_t kb = sKb + buf * STGB;
        const uint32_t vb = sVb + buf * STGB;
        #pragma unroll
        for (int p = 0; p < 2; p++) {
            int idx = tid + p * 256;
            int r = idx >> 3, c = idx & 7;
            uint32_t so = (uint32_t)(r * KPAD + c * 8) * 2;
            cp16(kb + so, kh + ((size_t)(k0 + r)) * DEP + c * 8);
            cp16(vb + so, vh + ((size_t)r) * SEQ + k0 + c * 8);
        }
        CP_COMMIT();
    };

    issue_tile(0, 0);

    for (int it = 0; it < 32; it++) {
        CP_WAIT0();
        __syncthreads();
        if (it < 31) issue_tile(it + 1, (it + 1) & 1);

        const uint32_t aK = aK0 + (it & 1) * STGB;
        const uint32_t aV = aV0 + (it & 1) * STGB;

        // mask bit-words for this 64-col tile (2 rows x 64 bits)
        const uint2 w1 = *(const uint2*)(mb1 + 2 * it);
        const uint2 w2 = *(const uint2*)(mb2 + 2 * it);

        // ---- S = Q K^T ----
        float S[8][4];
        #pragma unroll
        for (int nt = 0; nt < 8; nt++)
            #pragma unroll
            for (int i = 0; i < 4; i++) S[nt][i] = 0.f;

        #pragma unroll
        for (int ks = 0; ks < 4; ks++) {
            #pragma unroll
            for (int ntp = 0; ntp < 4; ntp++) {
                uint32_t b0, b1, b2, b3;
                ldsm4(b0, b1, b2, b3, aK + ntp * (16 * ROWB) + ks * 32);
                mma_f16(S[2 * ntp],     qhi[ks], b0, b1);
                mma_f16(S[2 * ntp + 1], qhi[ks], b2, b3);
            }
        }

        // ---- softmax: p = masked ? 0 : 2^S; permuted bit index: sh = 8a + r ----
        uint32_t phi01[8], phi23[8];
        #pragma unroll
        for (int nt = 0; nt < 8; nt++) {
            const uint32_t wa = (nt < 4) ? w1.x : w1.y;
            const uint32_t wb = (nt < 4) ? w2.x : w2.y;
            const int col32 = (nt * 8 + c0) & 31;
            const int sh = ((col32 & 3) << 3) | (col32 >> 2);
            float p0 = ex2(S[nt][0]);
            float p1 = ex2(S[nt][1]);
            float p2 = ex2(S[nt][2]);
            float p3 = ex2(S[nt][3]);
            p0 = ((wa >> sh) & 1u) ? 0.f : p0;
            p1 = ((wa >> (sh + 8)) & 1u) ? 0.f : p1;
            p2 = ((wb >> sh) & 1u) ? 0.f : p2;
            p3 = ((wb >> (sh + 8)) & 1u) ? 0.f : p3;
            lg  += p0 + p1;
            lg8 += p2 + p3;
            phi01[nt] = pack_h(p0, p1);
            phi23[nt] = pack_h(p2, p3);
        }

        // ---- O += P V ----
        #pragma unroll
        for (int ks = 0; ks < 4; ks++) {
            uint32_t pa[4] = {phi01[2 * ks], phi23[2 * ks], phi01[2 * ks + 1], phi23[2 * ks + 1]};
            #pragma unroll
            for (int ntp = 0; ntp < 4; ntp++) {
                uint32_t b0, b1, b2, b3;
                ldsm4(b0, b1, b2, b3, aV + ntp * (16 * ROWB) + ks * 32);
                mma_f16(O[2 * ntp],     pa, b0, b1);
                mma_f16(O[2 * ntp + 1], pa, b2, b3);
            }
        }
    }

    // reduce row sums across the 4 lanes sharing each row
    lg  += __shfl_xor_sync(0xffffffffu, lg, 1);
    lg  += __shfl_xor_sync(0xffffffffu, lg, 2);
    lg8 += __shfl_xor_sync(0xffffffffu, lg8, 1);
    lg8 += __shfl_xor_sync(0xffffffffu, lg8, 2);
    const float inv1 = 1.f / lg, inv2 = 1.f / lg8;

    float* o1 = out + ((size_t)b * SEQ + row0 + g) * DMOD + h * DEP + c0;
    float* o2 = out + ((size_t)b * SEQ + row0 + g + 8) * DMOD + h * DEP + c0;
    #pragma unroll
    for (int nt = 0; nt < 8; nt++) {
        float2 w1v = make_float2(O[nt][0] * inv1, O[nt][1] * inv1);
        float2 w2v = make_float2(O[nt][2] * inv2, O[nt][3] * inv2);
        *(float2*)(o1 + nt * 8) = w1v;
        *(float2*)(o2 + nt * 8) = w2v;
    }
}

// ---------------- launch ----------------
extern "C" void kernel_launch(void* const* d_in, const int* in_sizes, int n_in,
                              void* d_out, int out_size) {
    const float* x    = (const float*)d_in[0];
    const float* mask = (const float*)d_in[1];
    const float* Wq   = (const float*)d_in[2];
    const float* bq   = (const float*)d_in[3];
    const float* Wk   = (const float*)d_in[4];
    const float* bk   = (const float*)d_in[5];
    const float* Wv   = (const float*)d_in[6];
    const float* bv   = (const float*)d_in[7];
    float* out = (float*)d_out;

    cudaFuncSetAttribute(qkv_mma, cudaFuncAttributeMaxDynamicSharedMemorySize, 2 * QSTG);

    prep_all<<<MASK_BLOCKS + PREPX_BLOCKS + PREPW_BLOCKS, 256>>>(mask, x, Wq, Wk, Wv);

    dim3 gqkv(DMOD / 128, (NB * SEQ) / 64, 3);           // (4, 64, 3) = 768 CTAs
    qkv_mma<<<gqkv, 128, 2 * QSTG>>>(bq, bk, bv);

    dim3 gattn(SEQ / 128, HB);                           // (16, 16) = 256 CTAs
    attn_mma<<<gattn, 256>>>(out);
}